// round 2
// baseline (speedup 1.0000x reference)
#include <cuda_runtime.h>
#include <cuda_bf16.h>
#include <cstdint>

// SDDMM: out[e] = <src_feat[src_idx[e]], dst_feat[dst_idx[e]]>, D=64 fp32.
// 16 lanes per edge; each lane loads one float4 from each gathered row
// (rows are 256B contiguous -> perfectly coalesced, sector-exact), then
// a 4-step shfl_xor reduction within the 16-lane group.

#define D_FEAT 64

__global__ void __launch_bounds__(256) sddmm_edge_dot_kernel(
    const int* __restrict__ src_idx,
    const int* __restrict__ dst_idx,
    const float* __restrict__ src_feat,
    const float* __restrict__ dst_feat,
    float* __restrict__ out,
    int n_edges)
{
    int gid  = blockIdx.x * blockDim.x + threadIdx.x;
    int e    = gid >> 4;        // edge index (16 lanes per edge)
    int lane = gid & 15;        // position within the 16-lane group
    if (e >= n_edges) return;

    int s = __ldg(src_idx + e); // uniform across the 16-lane group (L1 broadcast)
    int d = __ldg(dst_idx + e);

    const float4* srow = reinterpret_cast<const float4*>(src_feat + (size_t)s * D_FEAT);
    const float4* drow = reinterpret_cast<const float4*>(dst_feat + (size_t)d * D_FEAT);

    float4 a = __ldg(srow + lane);   // 16 lanes x 16B = full 256B row, coalesced
    float4 b = __ldg(drow + lane);

    float sum = fmaf(a.x, b.x, fmaf(a.y, b.y, fmaf(a.z, b.z, a.w * b.w)));

    // Reduce across the 16-lane group (groups are lane-aligned within the warp).
    sum += __shfl_xor_sync(0xffffffffu, sum, 8);
    sum += __shfl_xor_sync(0xffffffffu, sum, 4);
    sum += __shfl_xor_sync(0xffffffffu, sum, 2);
    sum += __shfl_xor_sync(0xffffffffu, sum, 1);

    if (lane == 0) out[e] = sum;
}

extern "C" void kernel_launch(void* const* d_in, const int* in_sizes, int n_in,
                              void* d_out, int out_size)
{
    const int*   src_idx  = (const int*)d_in[0];
    const int*   dst_idx  = (const int*)d_in[1];
    const float* src_feat = (const float*)d_in[2];
    const float* dst_feat = (const float*)d_in[3];
    float*       out      = (float*)d_out;

    int n_edges = in_sizes[0];

    const int threads = 256;
    long long total_threads = (long long)n_edges * 16;
    int blocks = (int)((total_threads + threads - 1) / threads);

    sddmm_edge_dot_kernel<<<blocks, threads>>>(src_idx, dst_idx, src_feat, dst_feat,
                                               out, n_edges);
}

// round 4
// speedup vs baseline: 1.6203x; 1.6203x over previous
#include <cuda_runtime.h>
#include <cuda_bf16.h>
#include <cstdint>

// SDDMM: out[e] = <src_feat[src_idx[e]], dst_feat[dst_idx[e]]>, D=64 fp32.
// 8 lanes per edge; each lane loads 2x float4 (32B) from each gathered row.
// Per LDG.128 instruction, each edge's 8 lanes cover exactly one full 128B
// line (sector- and wavefront-exact). All 4 feature loads are independent
// and front-batched for MLP; 3-step shfl_xor reduction per 8-lane group.

#define D_FEAT 64

__global__ void __launch_bounds__(256) sddmm_edge_dot_kernel(
    const int* __restrict__ src_idx,
    const int* __restrict__ dst_idx,
    const float* __restrict__ src_feat,
    const float* __restrict__ dst_feat,
    float* __restrict__ out,
    int n_edges)
{
    int gid  = blockIdx.x * blockDim.x + threadIdx.x;
    int e    = gid >> 3;        // edge index (8 lanes per edge)
    int lane = gid & 7;         // position within the 8-lane group
    if (e >= n_edges) return;

    int s = __ldg(src_idx + e); // uniform across the 8-lane group
    int d = __ldg(dst_idx + e);

    const float4* srow = reinterpret_cast<const float4*>(src_feat + (size_t)s * D_FEAT);
    const float4* drow = reinterpret_cast<const float4*>(dst_feat + (size_t)d * D_FEAT);

    // 4 independent 16B loads in flight per thread.
    // lane       -> line 0 of the row (8 lanes x 16B = 128B)
    // lane + 8   -> line 1 of the row
    float4 a0 = __ldg(srow + lane);
    float4 a1 = __ldg(srow + lane + 8);
    float4 b0 = __ldg(drow + lane);
    float4 b1 = __ldg(drow + lane + 8);

    float sum;
    sum = fmaf(a0.x, b0.x, a1.x * b1.x);
    sum = fmaf(a0.y, b0.y, sum);
    sum = fmaf(a1.y, b1.y, sum);
    sum = fmaf(a0.z, b0.z, sum);
    sum = fmaf(a1.z, b1.z, sum);
    sum = fmaf(a0.w, b0.w, sum);
    sum = fmaf(a1.w, b1.w, sum);

    // Reduce across the 8-lane group (groups are lane-aligned within the warp).
    sum += __shfl_xor_sync(0xffffffffu, sum, 4);
    sum += __shfl_xor_sync(0xffffffffu, sum, 2);
    sum += __shfl_xor_sync(0xffffffffu, sum, 1);

    if (lane == 0) out[e] = sum;
}

extern "C" void kernel_launch(void* const* d_in, const int* in_sizes, int n_in,
                              void* d_out, int out_size)
{
    const int*   src_idx  = (const int*)d_in[0];
    const int*   dst_idx  = (const int*)d_in[1];
    const float* src_feat = (const float*)d_in[2];
    const float* dst_feat = (const float*)d_in[3];
    float*       out      = (float*)d_out;

    int n_edges = in_sizes[0];

    const int threads = 256;
    long long total_threads = (long long)n_edges * 8;
    int blocks = (int)((total_threads + threads - 1) / threads);

    sddmm_edge_dot_kernel<<<blocks, threads>>>(src_idx, dst_idx, src_feat, dst_feat,
                                               out, n_edges);
}

// round 5
// speedup vs baseline: 1.7807x; 1.0990x over previous
#include <cuda_runtime.h>
#include <cuda_bf16.h>
#include <cstdint>

// SDDMM: out[e] = <src_feat[src_idx[e]], dst_feat[dst_idx[e]]>, D=64 fp32.
// 8 lanes per edge-PAIR-slot; each thread handles 2 adjacent edges (2g, 2g+1).
// Per edge, each lane loads 2x float4 (32B): one LDG.128 instruction covers
// exactly one full 128B line per edge (wavefront-exact). 8 independent
// feature loads + 1 int2 index load are front-batched (MLP ~9).
// 3-step shfl_xor reduction per 8-lane group; lane 0 writes a float2.

#define D_FEAT 64

__global__ void __launch_bounds__(256) sddmm_edge_dot_kernel(
    const int* __restrict__ src_idx,
    const int* __restrict__ dst_idx,
    const float* __restrict__ src_feat,
    const float* __restrict__ dst_feat,
    float* __restrict__ out,
    int n_edges)
{
    int gid  = blockIdx.x * blockDim.x + threadIdx.x;
    int g    = gid >> 3;        // edge-pair index
    int lane = gid & 7;         // position within the 8-lane group
    int e0   = g * 2;
    if (e0 >= n_edges) return;

    // Both indices of the pair in one 8B load each (E is even; arrays 8B-aligned).
    int2 sp = __ldg(reinterpret_cast<const int2*>(src_idx) + g);
    int2 dp = __ldg(reinterpret_cast<const int2*>(dst_idx) + g);

    const float4* srow0 = reinterpret_cast<const float4*>(src_feat + (size_t)sp.x * D_FEAT);
    const float4* drow0 = reinterpret_cast<const float4*>(dst_feat + (size_t)dp.x * D_FEAT);
    const float4* srow1 = reinterpret_cast<const float4*>(src_feat + (size_t)sp.y * D_FEAT);
    const float4* drow1 = reinterpret_cast<const float4*>(dst_feat + (size_t)dp.y * D_FEAT);

    // 8 independent 16B loads in flight.
    float4 a0 = __ldg(srow0 + lane);
    float4 a1 = __ldg(srow0 + lane + 8);
    float4 b0 = __ldg(drow0 + lane);
    float4 b1 = __ldg(drow0 + lane + 8);
    float4 c0 = __ldg(srow1 + lane);
    float4 c1 = __ldg(srow1 + lane + 8);
    float4 e1v0 = __ldg(drow1 + lane);
    float4 e1v1 = __ldg(drow1 + lane + 8);

    float s0;
    s0 = fmaf(a0.x, b0.x, a1.x * b1.x);
    s0 = fmaf(a0.y, b0.y, s0);
    s0 = fmaf(a1.y, b1.y, s0);
    s0 = fmaf(a0.z, b0.z, s0);
    s0 = fmaf(a1.z, b1.z, s0);
    s0 = fmaf(a0.w, b0.w, s0);
    s0 = fmaf(a1.w, b1.w, s0);

    float s1;
    s1 = fmaf(c0.x, e1v0.x, c1.x * e1v1.x);
    s1 = fmaf(c0.y, e1v0.y, s1);
    s1 = fmaf(c1.y, e1v1.y, s1);
    s1 = fmaf(c0.z, e1v0.z, s1);
    s1 = fmaf(c1.z, e1v1.z, s1);
    s1 = fmaf(c0.w, e1v0.w, s1);
    s1 = fmaf(c1.w, e1v1.w, s1);

    // Reduce both sums across the 8-lane group.
    s0 += __shfl_xor_sync(0xffffffffu, s0, 4);
    s1 += __shfl_xor_sync(0xffffffffu, s1, 4);
    s0 += __shfl_xor_sync(0xffffffffu, s0, 2);
    s1 += __shfl_xor_sync(0xffffffffu, s1, 2);
    s0 += __shfl_xor_sync(0xffffffffu, s0, 1);
    s1 += __shfl_xor_sync(0xffffffffu, s1, 1);

    if (lane == 0) {
        if (e0 + 1 < n_edges) {
            *reinterpret_cast<float2*>(out + e0) = make_float2(s0, s1);
        } else {
            out[e0] = s0;
        }
    }
}

extern "C" void kernel_launch(void* const* d_in, const int* in_sizes, int n_in,
                              void* d_out, int out_size)
{
    const int*   src_idx  = (const int*)d_in[0];
    const int*   dst_idx  = (const int*)d_in[1];
    const float* src_feat = (const float*)d_in[2];
    const float* dst_feat = (const float*)d_in[3];
    float*       out      = (float*)d_out;

    int n_edges = in_sizes[0];
    int n_pairs = (n_edges + 1) / 2;

    const int threads = 256;
    long long total_threads = (long long)n_pairs * 8;
    int blocks = (int)((total_threads + threads - 1) / threads);

    sddmm_edge_dot_kernel<<<blocks, threads>>>(src_idx, dst_idx, src_feat, dst_feat,
                                               out, n_edges);
}

// round 6
// speedup vs baseline: 1.7836x; 1.0016x over previous
#include <cuda_runtime.h>
#include <cuda_bf16.h>
#include <cstdint>

// SDDMM: out[e] = <src_feat[src_idx[e]], dst_feat[dst_idx[e]]>, D=64 fp32.
// 8 lanes per group; each thread handles 4 adjacent edges (4g..4g+3).
// Per edge, each lane loads 2x float4 (32B): each LDG.128 instruction covers
// exactly one full 128B line per edge (wavefront-exact). 16 independent
// feature loads + 2 int4 index loads are front-batched (MLP ~17).
// 3-step shfl_xor reduction per 8-lane group; lane 0 writes a float4.

#define D_FEAT 64

__global__ void __launch_bounds__(256) sddmm_edge_dot_kernel(
    const int* __restrict__ src_idx,
    const int* __restrict__ dst_idx,
    const float* __restrict__ src_feat,
    const float* __restrict__ dst_feat,
    float* __restrict__ out,
    int n_edges)
{
    int gid  = blockIdx.x * blockDim.x + threadIdx.x;
    int g    = gid >> 3;        // edge-quad index
    int lane = gid & 7;         // position within the 8-lane group
    int e0   = g * 4;
    if (e0 >= n_edges) return;

    // All 4 indices of the quad in one 16B load each.
    int4 sq = __ldg(reinterpret_cast<const int4*>(src_idx) + g);
    int4 dq = __ldg(reinterpret_cast<const int4*>(dst_idx) + g);

    const float4* s0p = reinterpret_cast<const float4*>(src_feat + (size_t)sq.x * D_FEAT) + lane;
    const float4* s1p = reinterpret_cast<const float4*>(src_feat + (size_t)sq.y * D_FEAT) + lane;
    const float4* s2p = reinterpret_cast<const float4*>(src_feat + (size_t)sq.z * D_FEAT) + lane;
    const float4* s3p = reinterpret_cast<const float4*>(src_feat + (size_t)sq.w * D_FEAT) + lane;
    const float4* d0p = reinterpret_cast<const float4*>(dst_feat + (size_t)dq.x * D_FEAT) + lane;
    const float4* d1p = reinterpret_cast<const float4*>(dst_feat + (size_t)dq.y * D_FEAT) + lane;
    const float4* d2p = reinterpret_cast<const float4*>(dst_feat + (size_t)dq.z * D_FEAT) + lane;
    const float4* d3p = reinterpret_cast<const float4*>(dst_feat + (size_t)dq.w * D_FEAT) + lane;

    // 16 independent 16B loads in flight.
    float4 a0 = __ldg(s0p);     float4 a1 = __ldg(s0p + 8);
    float4 b0 = __ldg(d0p);     float4 b1 = __ldg(d0p + 8);
    float4 c0 = __ldg(s1p);     float4 c1 = __ldg(s1p + 8);
    float4 f0 = __ldg(d1p);     float4 f1 = __ldg(d1p + 8);
    float4 g0 = __ldg(s2p);     float4 g1 = __ldg(s2p + 8);
    float4 h0 = __ldg(d2p);     float4 h1 = __ldg(d2p + 8);
    float4 p0 = __ldg(s3p);     float4 p1 = __ldg(s3p + 8);
    float4 q0 = __ldg(d3p);     float4 q1 = __ldg(d3p + 8);

    float r0, r1, r2, r3;

    r0 = fmaf(a0.x, b0.x, a1.x * b1.x);
    r0 = fmaf(a0.y, b0.y, r0);  r0 = fmaf(a1.y, b1.y, r0);
    r0 = fmaf(a0.z, b0.z, r0);  r0 = fmaf(a1.z, b1.z, r0);
    r0 = fmaf(a0.w, b0.w, r0);  r0 = fmaf(a1.w, b1.w, r0);

    r1 = fmaf(c0.x, f0.x, c1.x * f1.x);
    r1 = fmaf(c0.y, f0.y, r1);  r1 = fmaf(c1.y, f1.y, r1);
    r1 = fmaf(c0.z, f0.z, r1);  r1 = fmaf(c1.z, f1.z, r1);
    r1 = fmaf(c0.w, f0.w, r1);  r1 = fmaf(c1.w, f1.w, r1);

    r2 = fmaf(g0.x, h0.x, g1.x * h1.x);
    r2 = fmaf(g0.y, h0.y, r2);  r2 = fmaf(g1.y, h1.y, r2);
    r2 = fmaf(g0.z, h0.z, r2);  r2 = fmaf(g1.z, h1.z, r2);
    r2 = fmaf(g0.w, h0.w, r2);  r2 = fmaf(g1.w, h1.w, r2);

    r3 = fmaf(p0.x, q0.x, p1.x * q1.x);
    r3 = fmaf(p0.y, q0.y, r3);  r3 = fmaf(p1.y, q1.y, r3);
    r3 = fmaf(p0.z, q0.z, r3);  r3 = fmaf(p1.z, q1.z, r3);
    r3 = fmaf(p0.w, q0.w, r3);  r3 = fmaf(p1.w, q1.w, r3);

    // Reduce all 4 sums across the 8-lane group.
    r0 += __shfl_xor_sync(0xffffffffu, r0, 4);
    r1 += __shfl_xor_sync(0xffffffffu, r1, 4);
    r2 += __shfl_xor_sync(0xffffffffu, r2, 4);
    r3 += __shfl_xor_sync(0xffffffffu, r3, 4);
    r0 += __shfl_xor_sync(0xffffffffu, r0, 2);
    r1 += __shfl_xor_sync(0xffffffffu, r1, 2);
    r2 += __shfl_xor_sync(0xffffffffu, r2, 2);
    r3 += __shfl_xor_sync(0xffffffffu, r3, 2);
    r0 += __shfl_xor_sync(0xffffffffu, r0, 1);
    r1 += __shfl_xor_sync(0xffffffffu, r1, 1);
    r2 += __shfl_xor_sync(0xffffffffu, r2, 1);
    r3 += __shfl_xor_sync(0xffffffffu, r3, 1);

    if (lane == 0) {
        if (e0 + 3 < n_edges) {
            *reinterpret_cast<float4*>(out + e0) = make_float4(r0, r1, r2, r3);
        } else {
            out[e0] = r0;
            if (e0 + 1 < n_edges) out[e0 + 1] = r1;
            if (e0 + 2 < n_edges) out[e0 + 2] = r2;
        }
    }
}

extern "C" void kernel_launch(void* const* d_in, const int* in_sizes, int n_in,
                              void* d_out, int out_size)
{
    const int*   src_idx  = (const int*)d_in[0];
    const int*   dst_idx  = (const int*)d_in[1];
    const float* src_feat = (const float*)d_in[2];
    const float* dst_feat = (const float*)d_in[3];
    float*       out      = (float*)d_out;

    int n_edges = in_sizes[0];
    int n_quads = (n_edges + 3) / 4;

    const int threads = 256;
    long long total_threads = (long long)n_quads * 8;
    int blocks = (int)((total_threads + threads - 1) / threads);

    sddmm_edge_dot_kernel<<<blocks, threads>>>(src_idx, dst_idx, src_feat, dst_feat,
                                               out, n_edges);
}